// round 15
// baseline (speedup 1.0000x reference)
#include <cuda_runtime.h>
#include <cuda_fp16.h>
#include <cstdint>

#define T_TOK   8192
#define DMODEL  1024
#define DFF     4096
#define NEXP    8
#define MAX_SLOTS 17408          // 16384 assignments + per-expert pad to 128
#define MAX_TILES 136            // MAX_SLOTS / 128
#define KC 64                    // k halves per chunk (128 B per row)
#define SW 36                    // uint32 words per row (32 used + 4 pad); conflict-free
#define PLANE_W (128 * SW)       // 4608 words per plane
#define A_OFF 0
#define B_OFF PLANE_W
#define STAGE_W (2 * PLANE_W)    // 9216 words = 36864 B
#define NSTAGE 2
#define NTHR 128                 // 4 warps per CTA, 2 CTAs/SM
#define SMEM_BYTES (NSTAGE * STAGE_W * 4)   // 73728 B

// prep_kernel flat-grid region sizes
#define PREP_RESET_BLKS 68                               // MAX_SLOTS / 256
#define PREP_CVTX_BLKS  (T_TOK * DMODEL / 4 / 256)       // 8192
#define PREP_W_BLKS     (NEXP * (DFF / 32) * (DMODEL / 32))  // 32768 (each of w1, w2)
#define PREP_TOTAL (PREP_RESET_BLKS + PREP_CVTX_BLKS + 2 * PREP_W_BLKS)

// ---------------- device scratch (no allocation allowed) ----------------
__device__ __half g_xh [(size_t)T_TOK * DMODEL];        // fp16 x (16 MB)
__device__ __half g_w1h[(size_t)NEXP * DFF * DMODEL];   // fp16 w1^T [e][n][k] (64 MB)
__device__ __half g_w2h[(size_t)NEXP * DMODEL * DFF];   // fp16 w2^T [e][n][k] (64 MB)
__device__ __half g_hh [(size_t)MAX_SLOTS * DFF];       // fp16 hidden acts (143 MB)
__device__ float  g_y  [(size_t)MAX_SLOTS * DMODEL];    // gated per-slot outputs (71 MB)
__device__ int   g_slot_token[MAX_SLOTS];
__device__ float g_slot_gate[MAX_SLOTS];
__device__ int   g_tok_slot[T_TOK * 2];                 // slot of each (token, k) assignment
__device__ int   g_counts[NEXP];
__device__ int   g_offsets[NEXP];
__device__ int   g_tile_expert[MAX_TILES];
__device__ int   g_tok_expert[T_TOK * 2];
__device__ float g_tok_gate[T_TOK * 2];

// ---------------- helpers ----------------
__device__ __forceinline__ void mma_f16(float c[4], const uint32_t a[4], const uint32_t b[2]) {
    asm volatile(
        "mma.sync.aligned.m16n8k16.row.col.f32.f16.f16.f32 "
        "{%0,%1,%2,%3}, {%4,%5,%6,%7}, {%8,%9}, {%0,%1,%2,%3};\n"
        : "+f"(c[0]), "+f"(c[1]), "+f"(c[2]), "+f"(c[3])
        : "r"(a[0]), "r"(a[1]), "r"(a[2]), "r"(a[3]), "r"(b[0]), "r"(b[1]));
}
__device__ __forceinline__ void cp16(uint32_t smem_addr, const void* gmem, int src_bytes) {
    asm volatile("cp.async.cg.shared.global [%0], [%1], 16, %2;\n"
                 :: "r"(smem_addr), "l"(gmem), "r"(src_bytes));
}
__device__ __forceinline__ void cp_commit() {
    asm volatile("cp.async.commit_group;\n" ::: "memory");
}
__device__ __forceinline__ void cp_wait0() {
    asm volatile("cp.async.wait_group 0;\n" ::: "memory");
}

// ---------------- 1: prep — reset + cvt_x + transpose/cvt w1, w2 (one launch) ----------------
__device__ __forceinline__ void transpose_cvt_block(
    const float* __restrict__ src, __half* __restrict__ dst,
    int K, int N, int e, int n0, int k0, int tid)
{
    __shared__ float tile[32][33];
    const float* s = src + (size_t)e * K * N;
    __half* oh = dst + (size_t)e * K * N;
    int tx = tid & 31, ty = tid >> 5;   // 32 x 8
    #pragma unroll
    for (int j = 0; j < 32; j += 8)
        tile[ty + j][tx] = s[(size_t)(k0 + ty + j) * N + n0 + tx];
    __syncthreads();
    #pragma unroll
    for (int j = 0; j < 32; j += 8) {
        int n = n0 + ty + j;
        oh[(size_t)n * K + k0 + tx] = __float2half_rn(tile[tx][ty + j]);
    }
}

__global__ __launch_bounds__(256) void prep_kernel(
    const float* __restrict__ x, const float* __restrict__ w1, const float* __restrict__ w2)
{
    int b = blockIdx.x;
    int tid = threadIdx.x;
    if (b < PREP_RESET_BLKS) {
        int i = b * 256 + tid;
        if (i < MAX_SLOTS) g_slot_token[i] = -1;
        if (i < NEXP) g_counts[i] = 0;
        return;
    }
    b -= PREP_RESET_BLKS;
    if (b < PREP_CVTX_BLKS) {
        size_t i = (size_t)b * 256 + tid;
        float4 v = ((const float4*)x)[i];
        __half2* oh = (__half2*)(g_xh + 4 * i);
        oh[0] = __halves2half2(__float2half_rn(v.x), __float2half_rn(v.y));
        oh[1] = __halves2half2(__float2half_rn(v.z), __float2half_rn(v.w));
        return;
    }
    b -= PREP_CVTX_BLKS;
    if (b < PREP_W_BLKS) {
        // w1: K=DMODEL (32 k-blocks), N=DFF (128 n-blocks)
        int e = b / (128 * 32);
        int rem = b % (128 * 32);
        int k0 = (rem / 128) * 32;
        int n0 = (rem % 128) * 32;
        transpose_cvt_block(w1, g_w1h, DMODEL, DFF, e, n0, k0, tid);
        return;
    }
    b -= PREP_W_BLKS;
    {
        // w2: K=DFF (128 k-blocks), N=DMODEL (32 n-blocks)
        int e = b / (128 * 32);
        int rem = b % (128 * 32);
        int k0 = (rem / 32) * 32;
        int n0 = (rem % 32) * 32;
        transpose_cvt_block(w2, g_w2h, DFF, DMODEL, e, n0, k0, tid);
    }
}

// ---------------- 2: router (one warp per token) ----------------
__global__ __launch_bounds__(256) void router_kernel(
    const float* __restrict__ x, const float* __restrict__ noise_u,
    const float* __restrict__ wg, const float* __restrict__ bg,
    const float* __restrict__ wn, const float* __restrict__ bn)
{
    __shared__ float sW[512][20];
    const int tid = threadIdx.x;
    const int wid = tid >> 5, lane = tid & 31;
    const int t = blockIdx.x * 8 + wid;

    float acc[16];
    #pragma unroll
    for (int j = 0; j < 16; j++) acc[j] = 0.f;

    for (int c = 0; c < 2; c++) {
        #pragma unroll
        for (int it = 0; it < 8; it++) {
            int idx = it * 256 + tid;
            int row = idx >> 2, qq = idx & 3;
            int grow = c * 512 + row;
            float4 v;
            if (qq < 2) v = *(const float4*)(wg + (size_t)grow * NEXP + qq * 4);
            else        v = *(const float4*)(wn + (size_t)grow * NEXP + (qq - 2) * 4);
            *(float4*)&sW[row][qq * 4] = v;
        }
        __syncthreads();

        const float* xr = x + (size_t)t * DMODEL + c * 512;
        for (int kk = lane; kk < 512; kk += 32) {
            float xv = xr[kk];
            float4 a0 = *(const float4*)&sW[kk][0];
            float4 a1 = *(const float4*)&sW[kk][4];
            float4 b0 = *(const float4*)&sW[kk][8];
            float4 b1 = *(const float4*)&sW[kk][12];
            acc[0]  += xv * a0.x; acc[1]  += xv * a0.y; acc[2]  += xv * a0.z; acc[3]  += xv * a0.w;
            acc[4]  += xv * a1.x; acc[5]  += xv * a1.y; acc[6]  += xv * a1.z; acc[7]  += xv * a1.w;
            acc[8]  += xv * b0.x; acc[9]  += xv * b0.y; acc[10] += xv * b0.z; acc[11] += xv * b0.w;
            acc[12] += xv * b1.x; acc[13] += xv * b1.y; acc[14] += xv * b1.z; acc[15] += xv * b1.w;
        }
        __syncthreads();
    }

    #pragma unroll
    for (int j = 0; j < 16; j++) {
        float v = acc[j];
        #pragma unroll
        for (int o = 16; o > 0; o >>= 1) v += __shfl_xor_sync(0xffffffffu, v, o);
        acc[j] = v;
    }

    if (lane == 0) {
        float v0 = -1e30f, v1 = -1e30f;
        int i0 = 0, i1 = 0;
        #pragma unroll
        for (int e = 0; e < NEXP; e++) {
            float lg = acc[e] + bg[e];
            float nl = acc[8 + e] + bn[e];
            float sp = fmaxf(nl, 0.f) + log1pf(expf(-fabsf(nl)));
            float nz = lg + noise_u[(size_t)t * NEXP + e] * sp;
            if (nz > v0)      { v1 = v0; i1 = i0; v0 = nz; i0 = e; }
            else if (nz > v1) { v1 = nz; i1 = e; }
        }
        float e1 = expf(v1 - v0);
        float s  = 1.f + e1;
        int o = t * 2;
        g_tok_expert[o]     = i0; g_tok_gate[o]     = 1.f / s;
        g_tok_expert[o + 1] = i1; g_tok_gate[o + 1] = e1 / s;
        atomicAdd(&g_counts[i0], 1);
        atomicAdd(&g_counts[i1], 1);
    }
}

// ---------------- 3: offsets + scatter (single block) ----------------
__global__ __launch_bounds__(256) void offsets_scatter_kernel() {
    __shared__ int sFill[NEXP];
    int tid = threadIdx.x;
    if (tid == 0) {
        int off = 0;
        for (int e = 0; e < NEXP; e++) {
            g_offsets[e] = off;
            int tiles = (g_counts[e] + 127) >> 7;
            for (int i = 0; i < tiles; i++) g_tile_expert[(off >> 7) + i] = e;
            off += tiles << 7;
        }
        for (int i = off >> 7; i < MAX_TILES; i++) g_tile_expert[i] = -1;
    }
    if (tid < NEXP) sFill[tid] = 0;
    __syncthreads();
    for (int i = tid; i < T_TOK * 2; i += 256) {
        int e = g_tok_expert[i];
        float gt = g_tok_gate[i];
        int pos = atomicAdd(&sFill[e], 1);
        int slot = g_offsets[e] + pos;
        g_slot_token[slot] = i >> 1;
        g_slot_gate[slot]  = gt;
        g_tok_slot[i]      = slot;
    }
}

// ================= plain-fp16 GEMM core: 4 warps (2m x 2n), 64x64 warp tiles =================
__device__ __forceinline__ void compute_chunk(
    const uint32_t* __restrict__ S, int wm, int wn, int g, int tg, float acc[4][8][4])
{
    #pragma unroll
    for (int step = 0; step < 4; step++) {
        const int kw = step * 8 + tg;
        uint32_t a[4][4], b[8][2];
        #pragma unroll
        for (int mt = 0; mt < 4; mt++) {
            int base = (wm * 64 + mt * 16 + g) * SW + kw;
            a[mt][0] = S[A_OFF + base];
            a[mt][1] = S[A_OFF + base + 8 * SW];
            a[mt][2] = S[A_OFF + base + 4];
            a[mt][3] = S[A_OFF + base + 8 * SW + 4];
        }
        #pragma unroll
        for (int nt = 0; nt < 8; nt++) {
            int base = (wn * 64 + nt * 8 + g) * SW + kw;
            b[nt][0] = S[B_OFF + base];
            b[nt][1] = S[B_OFF + base + 4];
        }
        #pragma unroll
        for (int mt = 0; mt < 4; mt++)
            #pragma unroll
            for (int nt = 0; nt < 8; nt++)
                mma_f16(acc[mt][nt], a[mt], b[nt]);
    }
}

// ---------------- 4: gemm1  h = fp16(relu(gather(X) @ w1[e] + b1)) ----------------
__global__ __launch_bounds__(NTHR, 2) void gemm1_kernel(const float* __restrict__ b1)
{
    const int tile = blockIdx.y;
    const int e = g_tile_expert[tile];
    if (e < 0) return;
    const int n0 = blockIdx.x * 128;
    const int base = tile * 128;

    extern __shared__ uint32_t smem[];
    __shared__ int sTok[128];

    const int tid = threadIdx.x;
    sTok[tid] = g_slot_token[base + tid];
    __syncthreads();

    const uint32_t smem_u32 = (uint32_t)__cvta_generic_to_shared(smem);

    const int qq = tid & 7, r0 = tid >> 3;
    const __half* srcA[8]; int szA[8];
    #pragma unroll
    for (int it = 0; it < 8; it++) {
        int r = r0 + 16 * it;
        int t = sTok[r];
        srcA[it] = g_xh + (size_t)(t < 0 ? 0 : t) * DMODEL + qq * 8;
        szA[it]  = (t >= 0) ? 16 : 0;
    }
    const __half* srcB0 = g_w1h + (size_t)e * DFF * DMODEL + (size_t)(n0 + r0) * DMODEL + qq * 8;
    const uint32_t dA0 = smem_u32 + ((A_OFF + r0 * SW + qq * 4) << 2);
    const uint32_t dB0 = smem_u32 + ((B_OFF + r0 * SW + qq * 4) << 2);

    const int NCHUNK = DMODEL / KC;   // 16
    const int wid = tid >> 5, lane = tid & 31;
    const int wm = wid >> 1, wn = wid & 1;
    const int g = lane >> 2, tg = lane & 3;

    float acc[4][8][4];
    #pragma unroll
    for (int i = 0; i < 4; i++)
        #pragma unroll
        for (int j = 0; j < 8; j++)
            #pragma unroll
            for (int k = 0; k < 4; k++) acc[i][j][k] = 0.f;

    // prologue: chunk 0 into stage 0
    #pragma unroll
    for (int it = 0; it < 8; it++) cp16(dA0 + it * (16 * SW * 4), srcA[it], szA[it]);
    #pragma unroll
    for (int it = 0; it < 8; it++) cp16(dB0 + it * (16 * SW * 4), srcB0 + (size_t)it * 16 * DMODEL, 16);
    cp_commit();

    for (int i = 0; i < NCHUNK; i++) {
        cp_wait0();
        __syncthreads();
        int pc = i + 1;
        if (pc < NCHUNK) {
            uint32_t sb = (pc & 1) * (STAGE_W * 4);
            int k0 = pc * KC;
            #pragma unroll
            for (int it = 0; it < 8; it++)
                cp16(dA0 + sb + it * (16 * SW * 4), srcA[it] + k0, szA[it]);
            #pragma unroll
            for (int it = 0; it < 8; it++)
                cp16(dB0 + sb + it * (16 * SW * 4), srcB0 + (size_t)it * 16 * DMODEL + k0, 16);
        }
        cp_commit();
        compute_chunk(smem + (i & 1) * STAGE_W, wm, wn, g, tg, acc);
    }

    const float* b1e = b1 + (size_t)e * DFF + n0;
    #pragma unroll
    for (int mt = 0; mt < 4; mt++) {
        int row = wm * 64 + mt * 16 + g;
        #pragma unroll
        for (int nt = 0; nt < 8; nt++) {
            int col = wn * 64 + nt * 8 + tg * 2;
            float bb0 = b1e[col], bb1 = b1e[col + 1];
            float y00 = fmaxf(acc[mt][nt][0] + bb0, 0.f);
            float y01 = fmaxf(acc[mt][nt][1] + bb1, 0.f);
            float y10 = fmaxf(acc[mt][nt][2] + bb0, 0.f);
            float y11 = fmaxf(acc[mt][nt][3] + bb1, 0.f);
            size_t o0 = (size_t)(base + row) * DFF + n0 + col;
            size_t o1 = (size_t)(base + row + 8) * DFF + n0 + col;
            *(__half2*)(g_hh + o0) = __halves2half2(__float2half_rn(y00), __float2half_rn(y01));
            *(__half2*)(g_hh + o1) = __halves2half2(__float2half_rn(y10), __float2half_rn(y11));
        }
    }
}

// ---------------- 5: gemm2  y[slot] = gate * (h @ w2[e] + b2)  (no atomics) ----------------
__global__ __launch_bounds__(NTHR, 2) void gemm2_kernel(const float* __restrict__ b2)
{
    const int tile = blockIdx.y;
    const int e = g_tile_expert[tile];
    if (e < 0) return;
    const int n0 = blockIdx.x * 128;
    const int base = tile * 128;

    extern __shared__ uint32_t smem[];
    __shared__ float sGate[128];

    const int tid = threadIdx.x;
    sGate[tid] = g_slot_gate[base + tid];
    __syncthreads();

    const uint32_t smem_u32 = (uint32_t)__cvta_generic_to_shared(smem);

    const int qq = tid & 7, r0 = tid >> 3;
    const __half* srcA0 = g_hh + (size_t)(base + r0) * DFF + qq * 8;
    const __half* srcB0 = g_w2h + (size_t)e * DMODEL * DFF + (size_t)(n0 + r0) * DFF + qq * 8;
    const uint32_t dA0 = smem_u32 + ((A_OFF + r0 * SW + qq * 4) << 2);
    const uint32_t dB0 = smem_u32 + ((B_OFF + r0 * SW + qq * 4) << 2);

    const int NCHUNK = DFF / KC;   // 64
    const int wid = tid >> 5, lane = tid & 31;
    const int wm = wid >> 1, wn = wid & 1;
    const int g = lane >> 2, tg = lane & 3;

    float acc[4][8][4];
    #pragma unroll
    for (int i = 0; i < 4; i++)
        #pragma unroll
        for (int j = 0; j < 8; j++)
            #pragma unroll
            for (int k = 0; k < 4; k++) acc[i][j][k] = 0.f;

    #pragma unroll
    for (int it = 0; it < 8; it++) cp16(dA0 + it * (16 * SW * 4), srcA0 + (size_t)it * 16 * DFF, 16);
    #pragma unroll
    for (int it = 0; it < 8; it++) cp16(dB0 + it * (16 * SW * 4), srcB0 + (size_t)it * 16 * DFF, 16);
    cp_commit();

    for (int i = 0; i < NCHUNK; i++) {
        cp_wait0();
        __syncthreads();
        int pc = i + 1;
        if (pc < NCHUNK) {
            uint32_t sb = (pc & 1) * (STAGE_W * 4);
            int k0 = pc * KC;
            #pragma unroll
            for (int it = 0; it < 8; it++)
                cp16(dA0 + sb + it * (16 * SW * 4), srcA0 + (size_t)it * 16 * DFF + k0, 16);
            #pragma unroll
            for (int it = 0; it < 8; it++)
                cp16(dB0 + sb + it * (16 * SW * 4), srcB0 + (size_t)it * 16 * DFF + k0, 16);
        }
        cp_commit();
        compute_chunk(smem + (i & 1) * STAGE_W, wm, wn, g, tg, acc);
    }

    const float* b2e = b2 + (size_t)e * DMODEL + n0;
    #pragma unroll
    for (int mt = 0; mt < 4; mt++) {
        int row = wm * 64 + mt * 16 + g;
        float gt0 = sGate[row], gt1 = sGate[row + 8];
        float* y0 = g_y + (size_t)(base + row) * DMODEL + n0;
        float* y1 = g_y + (size_t)(base + row + 8) * DMODEL + n0;
        #pragma unroll
        for (int nt = 0; nt < 8; nt++) {
            int col = wn * 64 + nt * 8 + tg * 2;
            float bb0 = b2e[col], bb1 = b2e[col + 1];
            float2 v0, v1;
            v0.x = gt0 * (acc[mt][nt][0] + bb0);
            v0.y = gt0 * (acc[mt][nt][1] + bb1);
            v1.x = gt1 * (acc[mt][nt][2] + bb0);
            v1.y = gt1 * (acc[mt][nt][3] + bb1);
            *(float2*)(y0 + col) = v0;
            *(float2*)(y1 + col) = v1;
        }
    }
}

// ---------------- 6: combine  out[t] = y[slot0(t)] + y[slot1(t)] ----------------
__global__ __launch_bounds__(256) void combine_kernel(float4* __restrict__ out) {
    int t = blockIdx.x;
    int s0 = g_tok_slot[2 * t], s1 = g_tok_slot[2 * t + 1];
    int i = threadIdx.x;
    const float4* y0 = (const float4*)(g_y + (size_t)s0 * DMODEL) + i;
    const float4* y1 = (const float4*)(g_y + (size_t)s1 * DMODEL) + i;
    float4 a = *y0, b = *y1;
    a.x += b.x; a.y += b.y; a.z += b.z; a.w += b.w;
    out[(size_t)t * (DMODEL / 4) + i] = a;
}

// ---------------- launch ----------------
extern "C" void kernel_launch(void* const* d_in, const int* in_sizes, int n_in,
                              void* d_out, int out_size)
{
    (void)in_sizes; (void)n_in; (void)out_size;
    const float* x       = (const float*)d_in[0];
    const float* noise_u = (const float*)d_in[1];
    const float* wg      = (const float*)d_in[2];
    const float* bg      = (const float*)d_in[3];
    const float* wn      = (const float*)d_in[4];
    const float* bn      = (const float*)d_in[5];
    const float* w1      = (const float*)d_in[6];
    const float* b1      = (const float*)d_in[7];
    const float* w2      = (const float*)d_in[8];
    const float* b2      = (const float*)d_in[9];
    float* out = (float*)d_out;

    cudaFuncSetAttribute(gemm1_kernel, cudaFuncAttributeMaxDynamicSharedMemorySize, SMEM_BYTES);
    cudaFuncSetAttribute(gemm2_kernel, cudaFuncAttributeMaxDynamicSharedMemorySize, SMEM_BYTES);

    prep_kernel<<<PREP_TOTAL, 256>>>(x, w1, w2);                 // launch 0
    router_kernel<<<T_TOK / 8, 256>>>(x, noise_u, wg, bg, wn, bn); // launch 1
    offsets_scatter_kernel<<<1, 256>>>();                        // launch 2
    gemm1_kernel<<<dim3(DFF / 128, MAX_TILES), NTHR, SMEM_BYTES>>>(b1);   // launch 3 -> ncu slot
    gemm2_kernel<<<dim3(DMODEL / 128, MAX_TILES), NTHR, SMEM_BYTES>>>(b2);
    combine_kernel<<<T_TOK, 256>>>((float4*)out);
}

// round 16
// speedup vs baseline: 1.0363x; 1.0363x over previous
#include <cuda_runtime.h>
#include <cuda_fp16.h>
#include <cstdint>

#define T_TOK   8192
#define DMODEL  1024
#define DFF     4096
#define NEXP    8
#define MAX_SLOTS 17408          // 16384 assignments + per-expert pad to 128
#define MAX_TILES 136            // MAX_SLOTS / 128
#define KC 64                    // k halves per chunk (128 B per row)
#define SW 36                    // uint32 words per row (32 used + 4 pad); conflict-free
#define PLANE_W (128 * SW)       // 4608 words per plane
#define A_OFF 0
#define B_OFF PLANE_W
#define STAGE_W (2 * PLANE_W)    // 9216 words = 36864 B
#define NSTAGE 2
#define NTHR 128                 // 4 warps per CTA, 3 CTAs/SM
#define SMEM_BYTES (NSTAGE * STAGE_W * 4)   // 73728 B (x3 CTAs = 221184 <= 228KB)

// prep_kernel flat-grid region sizes
#define PREP_RESET_BLKS 68                               // MAX_SLOTS / 256
#define PREP_CVTX_BLKS  (T_TOK * DMODEL / 4 / 256)       // 8192
#define PREP_W_BLKS     (NEXP * (DFF / 32) * (DMODEL / 32))  // 32768 (each of w1, w2)
#define PREP_TOTAL (PREP_RESET_BLKS + PREP_CVTX_BLKS + 2 * PREP_W_BLKS)

// ---------------- device scratch (no allocation allowed) ----------------
__device__ __half g_xh [(size_t)T_TOK * DMODEL];        // fp16 x (16 MB)
__device__ __half g_w1h[(size_t)NEXP * DFF * DMODEL];   // fp16 w1^T [e][n][k] (64 MB)
__device__ __half g_w2h[(size_t)NEXP * DMODEL * DFF];   // fp16 w2^T [e][n][k] (64 MB)
__device__ __half g_hh [(size_t)MAX_SLOTS * DFF];       // fp16 hidden acts (143 MB)
__device__ float  g_y  [(size_t)MAX_SLOTS * DMODEL];    // gated per-slot outputs (71 MB)
__device__ int   g_slot_token[MAX_SLOTS];
__device__ float g_slot_gate[MAX_SLOTS];
__device__ int   g_tok_slot[T_TOK * 2];                 // slot of each (token, k) assignment
__device__ int   g_counts[NEXP];
__device__ int   g_offsets[NEXP];
__device__ int   g_tile_expert[MAX_TILES];
__device__ int   g_tok_expert[T_TOK * 2];
__device__ float g_tok_gate[T_TOK * 2];

// ---------------- helpers ----------------
__device__ __forceinline__ void mma_f16(float c[4], const uint32_t a[4], const uint32_t b[2]) {
    asm volatile(
        "mma.sync.aligned.m16n8k16.row.col.f32.f16.f16.f32 "
        "{%0,%1,%2,%3}, {%4,%5,%6,%7}, {%8,%9}, {%0,%1,%2,%3};\n"
        : "+f"(c[0]), "+f"(c[1]), "+f"(c[2]), "+f"(c[3])
        : "r"(a[0]), "r"(a[1]), "r"(a[2]), "r"(a[3]), "r"(b[0]), "r"(b[1]));
}
__device__ __forceinline__ void cp16(uint32_t smem_addr, const void* gmem, int src_bytes) {
    asm volatile("cp.async.cg.shared.global [%0], [%1], 16, %2;\n"
                 :: "r"(smem_addr), "l"(gmem), "r"(src_bytes));
}
__device__ __forceinline__ void cp_commit() {
    asm volatile("cp.async.commit_group;\n" ::: "memory");
}
__device__ __forceinline__ void cp_wait0() {
    asm volatile("cp.async.wait_group 0;\n" ::: "memory");
}

// ---------------- 1: prep — reset + cvt_x + transpose/cvt w1, w2 (one launch) ----------------
__device__ __forceinline__ void transpose_cvt_block(
    const float* __restrict__ src, __half* __restrict__ dst,
    int K, int N, int e, int n0, int k0, int tid)
{
    __shared__ float tile[32][33];
    const float* s = src + (size_t)e * K * N;
    __half* oh = dst + (size_t)e * K * N;
    int tx = tid & 31, ty = tid >> 5;   // 32 x 8
    #pragma unroll
    for (int j = 0; j < 32; j += 8)
        tile[ty + j][tx] = s[(size_t)(k0 + ty + j) * N + n0 + tx];
    __syncthreads();
    #pragma unroll
    for (int j = 0; j < 32; j += 8) {
        int n = n0 + ty + j;
        oh[(size_t)n * K + k0 + tx] = __float2half_rn(tile[tx][ty + j]);
    }
}

__global__ __launch_bounds__(256) void prep_kernel(
    const float* __restrict__ x, const float* __restrict__ w1, const float* __restrict__ w2)
{
    int b = blockIdx.x;
    int tid = threadIdx.x;
    if (b < PREP_RESET_BLKS) {
        int i = b * 256 + tid;
        if (i < MAX_SLOTS) g_slot_token[i] = -1;
        if (i < NEXP) g_counts[i] = 0;
        return;
    }
    b -= PREP_RESET_BLKS;
    if (b < PREP_CVTX_BLKS) {
        size_t i = (size_t)b * 256 + tid;
        float4 v = ((const float4*)x)[i];
        __half2* oh = (__half2*)(g_xh + 4 * i);
        oh[0] = __halves2half2(__float2half_rn(v.x), __float2half_rn(v.y));
        oh[1] = __halves2half2(__float2half_rn(v.z), __float2half_rn(v.w));
        return;
    }
    b -= PREP_CVTX_BLKS;
    if (b < PREP_W_BLKS) {
        int e = b / (128 * 32);
        int rem = b % (128 * 32);
        int k0 = (rem / 128) * 32;
        int n0 = (rem % 128) * 32;
        transpose_cvt_block(w1, g_w1h, DMODEL, DFF, e, n0, k0, tid);
        return;
    }
    b -= PREP_W_BLKS;
    {
        int e = b / (128 * 32);
        int rem = b % (128 * 32);
        int k0 = (rem / 32) * 32;
        int n0 = (rem % 32) * 32;
        transpose_cvt_block(w2, g_w2h, DFF, DMODEL, e, n0, k0, tid);
    }
}

// ---------------- 2: router (one warp per token) ----------------
__global__ __launch_bounds__(256) void router_kernel(
    const float* __restrict__ x, const float* __restrict__ noise_u,
    const float* __restrict__ wg, const float* __restrict__ bg,
    const float* __restrict__ wn, const float* __restrict__ bn)
{
    __shared__ float sW[512][20];
    const int tid = threadIdx.x;
    const int wid = tid >> 5, lane = tid & 31;
    const int t = blockIdx.x * 8 + wid;

    float acc[16];
    #pragma unroll
    for (int j = 0; j < 16; j++) acc[j] = 0.f;

    for (int c = 0; c < 2; c++) {
        #pragma unroll
        for (int it = 0; it < 8; it++) {
            int idx = it * 256 + tid;
            int row = idx >> 2, qq = idx & 3;
            int grow = c * 512 + row;
            float4 v;
            if (qq < 2) v = *(const float4*)(wg + (size_t)grow * NEXP + qq * 4);
            else        v = *(const float4*)(wn + (size_t)grow * NEXP + (qq - 2) * 4);
            *(float4*)&sW[row][qq * 4] = v;
        }
        __syncthreads();

        const float* xr = x + (size_t)t * DMODEL + c * 512;
        for (int kk = lane; kk < 512; kk += 32) {
            float xv = xr[kk];
            float4 a0 = *(const float4*)&sW[kk][0];
            float4 a1 = *(const float4*)&sW[kk][4];
            float4 b0 = *(const float4*)&sW[kk][8];
            float4 b1 = *(const float4*)&sW[kk][12];
            acc[0]  += xv * a0.x; acc[1]  += xv * a0.y; acc[2]  += xv * a0.z; acc[3]  += xv * a0.w;
            acc[4]  += xv * a1.x; acc[5]  += xv * a1.y; acc[6]  += xv * a1.z; acc[7]  += xv * a1.w;
            acc[8]  += xv * b0.x; acc[9]  += xv * b0.y; acc[10] += xv * b0.z; acc[11] += xv * b0.w;
            acc[12] += xv * b1.x; acc[13] += xv * b1.y; acc[14] += xv * b1.z; acc[15] += xv * b1.w;
        }
        __syncthreads();
    }

    #pragma unroll
    for (int j = 0; j < 16; j++) {
        float v = acc[j];
        #pragma unroll
        for (int o = 16; o > 0; o >>= 1) v += __shfl_xor_sync(0xffffffffu, v, o);
        acc[j] = v;
    }

    if (lane == 0) {
        float v0 = -1e30f, v1 = -1e30f;
        int i0 = 0, i1 = 0;
        #pragma unroll
        for (int e = 0; e < NEXP; e++) {
            float lg = acc[e] + bg[e];
            float nl = acc[8 + e] + bn[e];
            float sp = fmaxf(nl, 0.f) + log1pf(expf(-fabsf(nl)));
            float nz = lg + noise_u[(size_t)t * NEXP + e] * sp;
            if (nz > v0)      { v1 = v0; i1 = i0; v0 = nz; i0 = e; }
            else if (nz > v1) { v1 = nz; i1 = e; }
        }
        float e1 = expf(v1 - v0);
        float s  = 1.f + e1;
        int o = t * 2;
        g_tok_expert[o]     = i0; g_tok_gate[o]     = 1.f / s;
        g_tok_expert[o + 1] = i1; g_tok_gate[o + 1] = e1 / s;
        atomicAdd(&g_counts[i0], 1);
        atomicAdd(&g_counts[i1], 1);
    }
}

// ---------------- 3: offsets + scatter (single block) ----------------
__global__ __launch_bounds__(256) void offsets_scatter_kernel() {
    __shared__ int sFill[NEXP];
    int tid = threadIdx.x;
    if (tid == 0) {
        int off = 0;
        for (int e = 0; e < NEXP; e++) {
            g_offsets[e] = off;
            int tiles = (g_counts[e] + 127) >> 7;
            for (int i = 0; i < tiles; i++) g_tile_expert[(off >> 7) + i] = e;
            off += tiles << 7;
        }
        for (int i = off >> 7; i < MAX_TILES; i++) g_tile_expert[i] = -1;
    }
    if (tid < NEXP) sFill[tid] = 0;
    __syncthreads();
    for (int i = tid; i < T_TOK * 2; i += 256) {
        int e = g_tok_expert[i];
        float gt = g_tok_gate[i];
        int pos = atomicAdd(&sFill[e], 1);
        int slot = g_offsets[e] + pos;
        g_slot_token[slot] = i >> 1;
        g_slot_gate[slot]  = gt;
        g_tok_slot[i]      = slot;
    }
}

// ================= plain-fp16 GEMM core: 4 warps (2m x 2n), 64x64 warp tiles =================
// b-fragments loaded inside the nt loop to shrink live register set (3 CTAs/SM fit).
__device__ __forceinline__ void compute_chunk(
    const uint32_t* __restrict__ S, int wm, int wn, int g, int tg, float acc[4][8][4])
{
    #pragma unroll
    for (int step = 0; step < 4; step++) {
        const int kw = step * 8 + tg;
        uint32_t a[4][4];
        #pragma unroll
        for (int mt = 0; mt < 4; mt++) {
            int base = (wm * 64 + mt * 16 + g) * SW + kw;
            a[mt][0] = S[A_OFF + base];
            a[mt][1] = S[A_OFF + base + 8 * SW];
            a[mt][2] = S[A_OFF + base + 4];
            a[mt][3] = S[A_OFF + base + 8 * SW + 4];
        }
        #pragma unroll
        for (int nt = 0; nt < 8; nt++) {
            uint32_t b[2];
            int base = (wn * 64 + nt * 8 + g) * SW + kw;
            b[0] = S[B_OFF + base];
            b[1] = S[B_OFF + base + 4];
            #pragma unroll
            for (int mt = 0; mt < 4; mt++)
                mma_f16(acc[mt][nt], a[mt], b);
        }
    }
}

// ---------------- 4: gemm1  h = fp16(relu(gather(X) @ w1[e] + b1)) ----------------
__global__ __launch_bounds__(NTHR, 3) void gemm1_kernel(const float* __restrict__ b1)
{
    const int tile = blockIdx.y;
    const int e = g_tile_expert[tile];
    if (e < 0) return;
    const int n0 = blockIdx.x * 128;
    const int base = tile * 128;

    extern __shared__ uint32_t smem[];
    __shared__ int sTok[128];

    const int tid = threadIdx.x;
    sTok[tid] = g_slot_token[base + tid];
    __syncthreads();

    const uint32_t smem_u32 = (uint32_t)__cvta_generic_to_shared(smem);

    const int qq = tid & 7, r0 = tid >> 3;
    const __half* srcA[8]; int szA[8];
    #pragma unroll
    for (int it = 0; it < 8; it++) {
        int r = r0 + 16 * it;
        int t = sTok[r];
        srcA[it] = g_xh + (size_t)(t < 0 ? 0 : t) * DMODEL + qq * 8;
        szA[it]  = (t >= 0) ? 16 : 0;
    }
    const __half* srcB0 = g_w1h + (size_t)e * DFF * DMODEL + (size_t)(n0 + r0) * DMODEL + qq * 8;
    const uint32_t dA0 = smem_u32 + ((A_OFF + r0 * SW + qq * 4) << 2);
    const uint32_t dB0 = smem_u32 + ((B_OFF + r0 * SW + qq * 4) << 2);

    const int NCHUNK = DMODEL / KC;   // 16
    const int wid = tid >> 5, lane = tid & 31;
    const int wm = wid >> 1, wn = wid & 1;
    const int g = lane >> 2, tg = lane & 3;

    float acc[4][8][4];
    #pragma unroll
    for (int i = 0; i < 4; i++)
        #pragma unroll
        for (int j = 0; j < 8; j++)
            #pragma unroll
            for (int k = 0; k < 4; k++) acc[i][j][k] = 0.f;

    // prologue: chunk 0 into stage 0
    #pragma unroll
    for (int it = 0; it < 8; it++) cp16(dA0 + it * (16 * SW * 4), srcA[it], szA[it]);
    #pragma unroll
    for (int it = 0; it < 8; it++) cp16(dB0 + it * (16 * SW * 4), srcB0 + (size_t)it * 16 * DMODEL, 16);
    cp_commit();

    for (int i = 0; i < NCHUNK; i++) {
        cp_wait0();
        __syncthreads();
        int pc = i + 1;
        if (pc < NCHUNK) {
            uint32_t sb = (pc & 1) * (STAGE_W * 4);
            int k0 = pc * KC;
            #pragma unroll
            for (int it = 0; it < 8; it++)
                cp16(dA0 + sb + it * (16 * SW * 4), srcA[it] + k0, szA[it]);
            #pragma unroll
            for (int it = 0; it < 8; it++)
                cp16(dB0 + sb + it * (16 * SW * 4), srcB0 + (size_t)it * 16 * DMODEL + k0, 16);
        }
        cp_commit();
        compute_chunk(smem + (i & 1) * STAGE_W, wm, wn, g, tg, acc);
    }

    const float* b1e = b1 + (size_t)e * DFF + n0;
    #pragma unroll
    for (int mt = 0; mt < 4; mt++) {
        int row = wm * 64 + mt * 16 + g;
        #pragma unroll
        for (int nt = 0; nt < 8; nt++) {
            int col = wn * 64 + nt * 8 + tg * 2;
            float bb0 = b1e[col], bb1 = b1e[col + 1];
            float y00 = fmaxf(acc[mt][nt][0] + bb0, 0.f);
            float y01 = fmaxf(acc[mt][nt][1] + bb1, 0.f);
            float y10 = fmaxf(acc[mt][nt][2] + bb0, 0.f);
            float y11 = fmaxf(acc[mt][nt][3] + bb1, 0.f);
            size_t o0 = (size_t)(base + row) * DFF + n0 + col;
            size_t o1 = (size_t)(base + row + 8) * DFF + n0 + col;
            *(__half2*)(g_hh + o0) = __halves2half2(__float2half_rn(y00), __float2half_rn(y01));
            *(__half2*)(g_hh + o1) = __halves2half2(__float2half_rn(y10), __float2half_rn(y11));
        }
    }
}

// ---------------- 5: gemm2  y[slot] = gate * (h @ w2[e] + b2)  (no atomics) ----------------
__global__ __launch_bounds__(NTHR, 3) void gemm2_kernel(const float* __restrict__ b2)
{
    const int tile = blockIdx.y;
    const int e = g_tile_expert[tile];
    if (e < 0) return;
    const int n0 = blockIdx.x * 128;
    const int base = tile * 128;

    extern __shared__ uint32_t smem[];
    __shared__ float sGate[128];

    const int tid = threadIdx.x;
    sGate[tid] = g_slot_gate[base + tid];
    __syncthreads();

    const uint32_t smem_u32 = (uint32_t)__cvta_generic_to_shared(smem);

    const int qq = tid & 7, r0 = tid >> 3;
    const __half* srcA0 = g_hh + (size_t)(base + r0) * DFF + qq * 8;
    const __half* srcB0 = g_w2h + (size_t)e * DMODEL * DFF + (size_t)(n0 + r0) * DFF + qq * 8;
    const uint32_t dA0 = smem_u32 + ((A_OFF + r0 * SW + qq * 4) << 2);
    const uint32_t dB0 = smem_u32 + ((B_OFF + r0 * SW + qq * 4) << 2);

    const int NCHUNK = DFF / KC;   // 64
    const int wid = tid >> 5, lane = tid & 31;
    const int wm = wid >> 1, wn = wid & 1;
    const int g = lane >> 2, tg = lane & 3;

    float acc[4][8][4];
    #pragma unroll
    for (int i = 0; i < 4; i++)
        #pragma unroll
        for (int j = 0; j < 8; j++)
            #pragma unroll
            for (int k = 0; k < 4; k++) acc[i][j][k] = 0.f;

    #pragma unroll
    for (int it = 0; it < 8; it++) cp16(dA0 + it * (16 * SW * 4), srcA0 + (size_t)it * 16 * DFF, 16);
    #pragma unroll
    for (int it = 0; it < 8; it++) cp16(dB0 + it * (16 * SW * 4), srcB0 + (size_t)it * 16 * DFF, 16);
    cp_commit();

    for (int i = 0; i < NCHUNK; i++) {
        cp_wait0();
        __syncthreads();
        int pc = i + 1;
        if (pc < NCHUNK) {
            uint32_t sb = (pc & 1) * (STAGE_W * 4);
            int k0 = pc * KC;
            #pragma unroll
            for (int it = 0; it < 8; it++)
                cp16(dA0 + sb + it * (16 * SW * 4), srcA0 + (size_t)it * 16 * DFF + k0, 16);
            #pragma unroll
            for (int it = 0; it < 8; it++)
                cp16(dB0 + sb + it * (16 * SW * 4), srcB0 + (size_t)it * 16 * DFF + k0, 16);
        }
        cp_commit();
        compute_chunk(smem + (i & 1) * STAGE_W, wm, wn, g, tg, acc);
    }

    const float* b2e = b2 + (size_t)e * DMODEL + n0;
    #pragma unroll
    for (int mt = 0; mt < 4; mt++) {
        int row = wm * 64 + mt * 16 + g;
        float gt0 = sGate[row], gt1 = sGate[row + 8];
        float* y0 = g_y + (size_t)(base + row) * DMODEL + n0;
        float* y1 = g_y + (size_t)(base + row + 8) * DMODEL + n0;
        #pragma unroll
        for (int nt = 0; nt < 8; nt++) {
            int col = wn * 64 + nt * 8 + tg * 2;
            float bb0 = b2e[col], bb1 = b2e[col + 1];
            float2 v0, v1;
            v0.x = gt0 * (acc[mt][nt][0] + bb0);
            v0.y = gt0 * (acc[mt][nt][1] + bb1);
            v1.x = gt1 * (acc[mt][nt][2] + bb0);
            v1.y = gt1 * (acc[mt][nt][3] + bb1);
            *(float2*)(y0 + col) = v0;
            *(float2*)(y1 + col) = v1;
        }
    }
}

// ---------------- 6: combine  out[t] = y[slot0(t)] + y[slot1(t)] ----------------
__global__ __launch_bounds__(256) void combine_kernel(float4* __restrict__ out) {
    int t = blockIdx.x;
    int s0 = g_tok_slot[2 * t], s1 = g_tok_slot[2 * t + 1];
    int i = threadIdx.x;
    const float4* y0 = (const float4*)(g_y + (size_t)s0 * DMODEL) + i;
    const float4* y1 = (const float4*)(g_y + (size_t)s1 * DMODEL) + i;
    float4 a = *y0, b = *y1;
    a.x += b.x; a.y += b.y; a.z += b.z; a.w += b.w;
    out[(size_t)t * (DMODEL / 4) + i] = a;
}

// ---------------- launch ----------------
extern "C" void kernel_launch(void* const* d_in, const int* in_sizes, int n_in,
                              void* d_out, int out_size)
{
    (void)in_sizes; (void)n_in; (void)out_size;
    const float* x       = (const float*)d_in[0];
    const float* noise_u = (const float*)d_in[1];
    const float* wg      = (const float*)d_in[2];
    const float* bg      = (const float*)d_in[3];
    const float* wn      = (const float*)d_in[4];
    const float* bn      = (const float*)d_in[5];
    const float* w1      = (const float*)d_in[6];
    const float* b1      = (const float*)d_in[7];
    const float* w2      = (const float*)d_in[8];
    const float* b2      = (const float*)d_in[9];
    float* out = (float*)d_out;

    cudaFuncSetAttribute(gemm1_kernel, cudaFuncAttributeMaxDynamicSharedMemorySize, SMEM_BYTES);
    cudaFuncSetAttribute(gemm2_kernel, cudaFuncAttributeMaxDynamicSharedMemorySize, SMEM_BYTES);

    prep_kernel<<<PREP_TOTAL, 256>>>(x, w1, w2);                 // launch 0
    router_kernel<<<T_TOK / 8, 256>>>(x, noise_u, wg, bg, wn, bn); // launch 1
    offsets_scatter_kernel<<<1, 256>>>();                        // launch 2
    gemm1_kernel<<<dim3(DFF / 128, MAX_TILES), NTHR, SMEM_BYTES>>>(b1);   // launch 3 -> ncu slot
    gemm2_kernel<<<dim3(DMODEL / 128, MAX_TILES), NTHR, SMEM_BYTES>>>(b2);
    combine_kernel<<<T_TOK, 256>>>((float4*)out);
}

// round 17
// speedup vs baseline: 1.0612x; 1.0241x over previous
#include <cuda_runtime.h>
#include <cuda_fp16.h>
#include <cstdint>

#define T_TOK   8192
#define DMODEL  1024
#define DFF     4096
#define NEXP    8
#define MAX_SLOTS 17408
#define MAX_TILES 136
#define KC 64                    // k halves per chunk (128 B per row)
#define SW 36                    // uint32 words per row; conflict-free
#define PLANE_W (128 * SW)
#define A_OFF 0
#define B_OFF PLANE_W
#define STAGE_W (2 * PLANE_W)    // 36864 B
#define NSTAGE 2
#define NTHR 128                 // 4 warps per CTA, 3 CTAs/SM
#define SMEM_BYTES (NSTAGE * STAGE_W * 4)   // 73728 B

#define PREP_RESET_BLKS 68
#define PREP_CVTX_BLKS  (T_TOK * DMODEL / 4 / 256)
#define PREP_W_BLKS     (NEXP * (DFF / 32) * (DMODEL / 32))
#define PREP_TOTAL (PREP_RESET_BLKS + PREP_CVTX_BLKS + 2 * PREP_W_BLKS)

// ---------------- device scratch ----------------
__device__ __half g_xh [(size_t)T_TOK * DMODEL];
__device__ __half g_w1h[(size_t)NEXP * DFF * DMODEL];
__device__ __half g_w2h[(size_t)NEXP * DMODEL * DFF];
__device__ __half g_hh [(size_t)MAX_SLOTS * DFF];
__device__ float  g_y  [(size_t)MAX_SLOTS * DMODEL];    // split-K partial 0
__device__ float  g_y2 [(size_t)MAX_SLOTS * DMODEL];    // split-K partial 1
__device__ int   g_slot_token[MAX_SLOTS];
__device__ float g_slot_gate[MAX_SLOTS];
__device__ int   g_tok_slot[T_TOK * 2];
__device__ int   g_counts[NEXP];
__device__ int   g_offsets[NEXP];
__device__ int   g_tile_expert[MAX_TILES];
__device__ int   g_tok_expert[T_TOK * 2];
__device__ float g_tok_gate[T_TOK * 2];

// ---------------- helpers ----------------
__device__ __forceinline__ void mma_f16(float c[4], const uint32_t a[4], const uint32_t b[2]) {
    asm volatile(
        "mma.sync.aligned.m16n8k16.row.col.f32.f16.f16.f32 "
        "{%0,%1,%2,%3}, {%4,%5,%6,%7}, {%8,%9}, {%0,%1,%2,%3};\n"
        : "+f"(c[0]), "+f"(c[1]), "+f"(c[2]), "+f"(c[3])
        : "r"(a[0]), "r"(a[1]), "r"(a[2]), "r"(a[3]), "r"(b[0]), "r"(b[1]));
}
__device__ __forceinline__ void ldsm_x4(uint32_t r[4], uint32_t addr) {
    asm volatile("ldmatrix.sync.aligned.m8n8.x4.shared.b16 {%0,%1,%2,%3}, [%4];"
        : "=r"(r[0]), "=r"(r[1]), "=r"(r[2]), "=r"(r[3]) : "r"(addr));
}
__device__ __forceinline__ void cp16(uint32_t smem_addr, const void* gmem, int src_bytes) {
    asm volatile("cp.async.cg.shared.global [%0], [%1], 16, %2;\n"
                 :: "r"(smem_addr), "l"(gmem), "r"(src_bytes));
}
__device__ __forceinline__ void cp_commit() {
    asm volatile("cp.async.commit_group;\n" ::: "memory");
}
__device__ __forceinline__ void cp_wait0() {
    asm volatile("cp.async.wait_group 0;\n" ::: "memory");
}

// ---------------- 1: prep — reset + cvt_x + transpose/cvt w1, w2 ----------------
__device__ __forceinline__ void transpose_cvt_block(
    const float* __restrict__ src, __half* __restrict__ dst,
    int K, int N, int e, int n0, int k0, int tid)
{
    __shared__ float tile[32][33];
    const float* s = src + (size_t)e * K * N;
    __half* oh = dst + (size_t)e * K * N;
    int tx = tid & 31, ty = tid >> 5;
    #pragma unroll
    for (int j = 0; j < 32; j += 8)
        tile[ty + j][tx] = s[(size_t)(k0 + ty + j) * N + n0 + tx];
    __syncthreads();
    #pragma unroll
    for (int j = 0; j < 32; j += 8) {
        int n = n0 + ty + j;
        oh[(size_t)n * K + k0 + tx] = __float2half_rn(tile[tx][ty + j]);
    }
}

__global__ __launch_bounds__(256) void prep_kernel(
    const float* __restrict__ x, const float* __restrict__ w1, const float* __restrict__ w2)
{
    int b = blockIdx.x;
    int tid = threadIdx.x;
    if (b < PREP_RESET_BLKS) {
        int i = b * 256 + tid;
        if (i < MAX_SLOTS) g_slot_token[i] = -1;
        if (i < NEXP) g_counts[i] = 0;
        return;
    }
    b -= PREP_RESET_BLKS;
    if (b < PREP_CVTX_BLKS) {
        size_t i = (size_t)b * 256 + tid;
        float4 v = ((const float4*)x)[i];
        __half2* oh = (__half2*)(g_xh + 4 * i);
        oh[0] = __halves2half2(__float2half_rn(v.x), __float2half_rn(v.y));
        oh[1] = __halves2half2(__float2half_rn(v.z), __float2half_rn(v.w));
        return;
    }
    b -= PREP_CVTX_BLKS;
    if (b < PREP_W_BLKS) {
        int e = b / (128 * 32);
        int rem = b % (128 * 32);
        int k0 = (rem / 128) * 32;
        int n0 = (rem % 128) * 32;
        transpose_cvt_block(w1, g_w1h, DMODEL, DFF, e, n0, k0, tid);
        return;
    }
    b -= PREP_W_BLKS;
    {
        int e = b / (128 * 32);
        int rem = b % (128 * 32);
        int k0 = (rem / 32) * 32;
        int n0 = (rem % 32) * 32;
        transpose_cvt_block(w2, g_w2h, DFF, DMODEL, e, n0, k0, tid);
    }
}

// ---------------- 2: router (one warp per token) ----------------
__global__ __launch_bounds__(256) void router_kernel(
    const float* __restrict__ x, const float* __restrict__ noise_u,
    const float* __restrict__ wg, const float* __restrict__ bg,
    const float* __restrict__ wn, const float* __restrict__ bn)
{
    __shared__ float sW[512][20];
    const int tid = threadIdx.x;
    const int wid = tid >> 5, lane = tid & 31;
    const int t = blockIdx.x * 8 + wid;

    float acc[16];
    #pragma unroll
    for (int j = 0; j < 16; j++) acc[j] = 0.f;

    for (int c = 0; c < 2; c++) {
        #pragma unroll
        for (int it = 0; it < 8; it++) {
            int idx = it * 256 + tid;
            int row = idx >> 2, qq = idx & 3;
            int grow = c * 512 + row;
            float4 v;
            if (qq < 2) v = *(const float4*)(wg + (size_t)grow * NEXP + qq * 4);
            else        v = *(const float4*)(wn + (size_t)grow * NEXP + (qq - 2) * 4);
            *(float4*)&sW[row][qq * 4] = v;
        }
        __syncthreads();

        const float* xr = x + (size_t)t * DMODEL + c * 512;
        for (int kk = lane; kk < 512; kk += 32) {
            float xv = xr[kk];
            float4 a0 = *(const float4*)&sW[kk][0];
            float4 a1 = *(const float4*)&sW[kk][4];
            float4 b0 = *(const float4*)&sW[kk][8];
            float4 b1 = *(const float4*)&sW[kk][12];
            acc[0]  += xv * a0.x; acc[1]  += xv * a0.y; acc[2]  += xv * a0.z; acc[3]  += xv * a0.w;
            acc[4]  += xv * a1.x; acc[5]  += xv * a1.y; acc[6]  += xv * a1.z; acc[7]  += xv * a1.w;
            acc[8]  += xv * b0.x; acc[9]  += xv * b0.y; acc[10] += xv * b0.z; acc[11] += xv * b0.w;
            acc[12] += xv * b1.x; acc[13] += xv * b1.y; acc[14] += xv * b1.z; acc[15] += xv * b1.w;
        }
        __syncthreads();
    }

    #pragma unroll
    for (int j = 0; j < 16; j++) {
        float v = acc[j];
        #pragma unroll
        for (int o = 16; o > 0; o >>= 1) v += __shfl_xor_sync(0xffffffffu, v, o);
        acc[j] = v;
    }

    if (lane == 0) {
        float v0 = -1e30f, v1 = -1e30f;
        int i0 = 0, i1 = 0;
        #pragma unroll
        for (int e = 0; e < NEXP; e++) {
            float lg = acc[e] + bg[e];
            float nl = acc[8 + e] + bn[e];
            float sp = fmaxf(nl, 0.f) + log1pf(expf(-fabsf(nl)));
            float nz = lg + noise_u[(size_t)t * NEXP + e] * sp;
            if (nz > v0)      { v1 = v0; i1 = i0; v0 = nz; i0 = e; }
            else if (nz > v1) { v1 = nz; i1 = e; }
        }
        float e1 = expf(v1 - v0);
        float s  = 1.f + e1;
        int o = t * 2;
        g_tok_expert[o]     = i0; g_tok_gate[o]     = 1.f / s;
        g_tok_expert[o + 1] = i1; g_tok_gate[o + 1] = e1 / s;
        atomicAdd(&g_counts[i0], 1);
        atomicAdd(&g_counts[i1], 1);
    }
}

// ---------------- 3: offsets + scatter (single block) ----------------
__global__ __launch_bounds__(256) void offsets_scatter_kernel() {
    __shared__ int sFill[NEXP];
    int tid = threadIdx.x;
    if (tid == 0) {
        int off = 0;
        for (int e = 0; e < NEXP; e++) {
            g_offsets[e] = off;
            int tiles = (g_counts[e] + 127) >> 7;
            for (int i = 0; i < tiles; i++) g_tile_expert[(off >> 7) + i] = e;
            off += tiles << 7;
        }
        for (int i = off >> 7; i < MAX_TILES; i++) g_tile_expert[i] = -1;
    }
    if (tid < NEXP) sFill[tid] = 0;
    __syncthreads();
    for (int i = tid; i < T_TOK * 2; i += 256) {
        int e = g_tok_expert[i];
        float gt = g_tok_gate[i];
        int pos = atomicAdd(&sFill[e], 1);
        int slot = g_offsets[e] + pos;
        g_slot_token[slot] = i >> 1;
        g_slot_gate[slot]  = gt;
        g_tok_slot[i]      = slot;
    }
}

// ================= fp16 GEMM core with ldmatrix: 4 warps (2m x 2n), 64x64 warp tiles =================
// Per k16-step: 4 LDSM.x4 for A (mt tiles), 4 LDSM.x4 for B (nt pairs, loaded in-loop).
__device__ __forceinline__ void compute_chunk(
    uint32_t sbase, const uint32_t* __restrict__ aOff, const uint32_t* __restrict__ bOff,
    float acc[4][8][4])
{
    #pragma unroll
    for (int step = 0; step < 4; step++) {
        uint32_t a[4][4];
        #pragma unroll
        for (int mt = 0; mt < 4; mt++)
            ldsm_x4(a[mt], sbase + aOff[mt] + step * 32);
        #pragma unroll
        for (int p = 0; p < 4; p++) {
            uint32_t b[4];
            ldsm_x4(b, sbase + bOff[p] + step * 32);
            #pragma unroll
            for (int mt = 0; mt < 4; mt++) {
                mma_f16(acc[mt][2 * p],     a[mt], &b[0]);
                mma_f16(acc[mt][2 * p + 1], a[mt], &b[2]);
            }
        }
    }
}

// per-thread ldmatrix byte offsets within a stage
__device__ __forceinline__ void make_ldsm_offsets(
    int lane, int wm, int wn, uint32_t aOff[4], uint32_t bOff[4])
{
    const int rsel = lane & 15;             // A row within 16-row tile
    const int ahw  = (lane >> 4) * 4;       // A k-half word offset (0 or 4)
    #pragma unroll
    for (int mt = 0; mt < 4; mt++)
        aOff[mt] = (uint32_t)(A_OFF + (wm * 64 + mt * 16 + rsel) * SW + ahw) << 2;
    const int q = lane >> 3;                // 0..3
    const int bnt = q >> 1;                 // which nt of the pair
    const int bhw = (q & 1) * 4;            // k-half word offset
    #pragma unroll
    for (int p = 0; p < 4; p++)
        bOff[p] = (uint32_t)(B_OFF + (wn * 64 + (2 * p + bnt) * 8 + (lane & 7)) * SW + bhw) << 2;
}

// ---------------- 4: gemm1  h = fp16(relu(gather(X) @ w1[e] + b1)) ----------------
__global__ __launch_bounds__(NTHR, 3) void gemm1_kernel(const float* __restrict__ b1)
{
    const int tile = blockIdx.y;
    const int e = g_tile_expert[tile];
    if (e < 0) return;
    const int n0 = blockIdx.x * 128;
    const int base = tile * 128;

    extern __shared__ uint32_t smem[];
    __shared__ int sTok[128];

    const int tid = threadIdx.x;
    sTok[tid] = g_slot_token[base + tid];
    __syncthreads();

    const uint32_t smem_u32 = (uint32_t)__cvta_generic_to_shared(smem);

    const int qq = tid & 7, r0 = tid >> 3;
    const __half* srcA[8]; int szA[8];
    #pragma unroll
    for (int it = 0; it < 8; it++) {
        int r = r0 + 16 * it;
        int t = sTok[r];
        srcA[it] = g_xh + (size_t)(t < 0 ? 0 : t) * DMODEL + qq * 8;
        szA[it]  = (t >= 0) ? 16 : 0;
    }
    const __half* srcB0 = g_w1h + (size_t)e * DFF * DMODEL + (size_t)(n0 + r0) * DMODEL + qq * 8;
    const uint32_t dA0 = smem_u32 + ((A_OFF + r0 * SW + qq * 4) << 2);
    const uint32_t dB0 = smem_u32 + ((B_OFF + r0 * SW + qq * 4) << 2);

    const int NCHUNK = DMODEL / KC;   // 16
    const int wid = tid >> 5, lane = tid & 31;
    const int wm = wid >> 1, wn = wid & 1;
    const int g = lane >> 2, tg = lane & 3;

    uint32_t aOff[4], bOff[4];
    make_ldsm_offsets(lane, wm, wn, aOff, bOff);

    float acc[4][8][4];
    #pragma unroll
    for (int i = 0; i < 4; i++)
        #pragma unroll
        for (int j = 0; j < 8; j++)
            #pragma unroll
            for (int k = 0; k < 4; k++) acc[i][j][k] = 0.f;

    #pragma unroll
    for (int it = 0; it < 8; it++) cp16(dA0 + it * (16 * SW * 4), srcA[it], szA[it]);
    #pragma unroll
    for (int it = 0; it < 8; it++) cp16(dB0 + it * (16 * SW * 4), srcB0 + (size_t)it * 16 * DMODEL, 16);
    cp_commit();

    for (int i = 0; i < NCHUNK; i++) {
        cp_wait0();
        __syncthreads();
        int pc = i + 1;
        if (pc < NCHUNK) {
            uint32_t sb = (pc & 1) * (STAGE_W * 4);
            int k0 = pc * KC;
            #pragma unroll
            for (int it = 0; it < 8; it++)
                cp16(dA0 + sb + it * (16 * SW * 4), srcA[it] + k0, szA[it]);
            #pragma unroll
            for (int it = 0; it < 8; it++)
                cp16(dB0 + sb + it * (16 * SW * 4), srcB0 + (size_t)it * 16 * DMODEL + k0, 16);
        }
        cp_commit();
        compute_chunk(smem_u32 + (i & 1) * (STAGE_W * 4), aOff, bOff, acc);
    }

    const float* b1e = b1 + (size_t)e * DFF + n0;
    #pragma unroll
    for (int mt = 0; mt < 4; mt++) {
        int row = wm * 64 + mt * 16 + g;
        #pragma unroll
        for (int nt = 0; nt < 8; nt++) {
            int col = wn * 64 + nt * 8 + tg * 2;
            float bb0 = b1e[col], bb1 = b1e[col + 1];
            float y00 = fmaxf(acc[mt][nt][0] + bb0, 0.f);
            float y01 = fmaxf(acc[mt][nt][1] + bb1, 0.f);
            float y10 = fmaxf(acc[mt][nt][2] + bb0, 0.f);
            float y11 = fmaxf(acc[mt][nt][3] + bb1, 0.f);
            size_t o0 = (size_t)(base + row) * DFF + n0 + col;
            size_t o1 = (size_t)(base + row + 8) * DFF + n0 + col;
            *(__half2*)(g_hh + o0) = __halves2half2(__float2half_rn(y00), __float2half_rn(y01));
            *(__half2*)(g_hh + o1) = __halves2half2(__float2half_rn(y10), __float2half_rn(y11));
        }
    }
}

// ---------------- 5: gemm2 split-K=2  y[kh][slot] = gate * (h[kh-half] @ w2[e] + b2?) ----------------
__global__ __launch_bounds__(NTHR, 3) void gemm2_kernel(const float* __restrict__ b2)
{
    const int tile = blockIdx.y;
    const int e = g_tile_expert[tile];
    if (e < 0) return;
    const int n0 = blockIdx.x * 128;
    const int base = tile * 128;
    const int kh = blockIdx.z;                 // 0 or 1
    const int kbase = kh * (DFF / 2);          // halves offset

    extern __shared__ uint32_t smem[];
    __shared__ float sGate[128];

    const int tid = threadIdx.x;
    sGate[tid] = g_slot_gate[base + tid];
    __syncthreads();

    const uint32_t smem_u32 = (uint32_t)__cvta_generic_to_shared(smem);

    const int qq = tid & 7, r0 = tid >> 3;
    const __half* srcA0 = g_hh + (size_t)(base + r0) * DFF + kbase + qq * 8;
    const __half* srcB0 = g_w2h + (size_t)e * DMODEL * DFF + (size_t)(n0 + r0) * DFF + kbase + qq * 8;
    const uint32_t dA0 = smem_u32 + ((A_OFF + r0 * SW + qq * 4) << 2);
    const uint32_t dB0 = smem_u32 + ((B_OFF + r0 * SW + qq * 4) << 2);

    const int NCHUNK = (DFF / 2) / KC;   // 32
    const int wid = tid >> 5, lane = tid & 31;
    const int wm = wid >> 1, wn = wid & 1;
    const int g = lane >> 2, tg = lane & 3;

    uint32_t aOff[4], bOff[4];
    make_ldsm_offsets(lane, wm, wn, aOff, bOff);

    float acc[4][8][4];
    #pragma unroll
    for (int i = 0; i < 4; i++)
        #pragma unroll
        for (int j = 0; j < 8; j++)
            #pragma unroll
            for (int k = 0; k < 4; k++) acc[i][j][k] = 0.f;

    #pragma unroll
    for (int it = 0; it < 8; it++) cp16(dA0 + it * (16 * SW * 4), srcA0 + (size_t)it * 16 * DFF, 16);
    #pragma unroll
    for (int it = 0; it < 8; it++) cp16(dB0 + it * (16 * SW * 4), srcB0 + (size_t)it * 16 * DFF, 16);
    cp_commit();

    for (int i = 0; i < NCHUNK; i++) {
        cp_wait0();
        __syncthreads();
        int pc = i + 1;
        if (pc < NCHUNK) {
            uint32_t sb = (pc & 1) * (STAGE_W * 4);
            int k0 = pc * KC;
            #pragma unroll
            for (int it = 0; it < 8; it++)
                cp16(dA0 + sb + it * (16 * SW * 4), srcA0 + (size_t)it * 16 * DFF + k0, 16);
            #pragma unroll
            for (int it = 0; it < 8; it++)
                cp16(dB0 + sb + it * (16 * SW * 4), srcB0 + (size_t)it * 16 * DFF + k0, 16);
        }
        cp_commit();
        compute_chunk(smem_u32 + (i & 1) * (STAGE_W * 4), aOff, bOff, acc);
    }

    const float* b2e = b2 + (size_t)e * DMODEL + n0;
    float* yout = (kh == 0) ? g_y : g_y2;
    const float bscale = (kh == 0) ? 1.f : 0.f;
    #pragma unroll
    for (int mt = 0; mt < 4; mt++) {
        int row = wm * 64 + mt * 16 + g;
        float gt0 = sGate[row], gt1 = sGate[row + 8];
        float* y0 = yout + (size_t)(base + row) * DMODEL + n0;
        float* y1 = yout + (size_t)(base + row + 8) * DMODEL + n0;
        #pragma unroll
        for (int nt = 0; nt < 8; nt++) {
            int col = wn * 64 + nt * 8 + tg * 2;
            float bb0 = bscale * b2e[col], bb1 = bscale * b2e[col + 1];
            float2 v0, v1;
            v0.x = gt0 * (acc[mt][nt][0] + bb0);
            v0.y = gt0 * (acc[mt][nt][1] + bb1);
            v1.x = gt1 * (acc[mt][nt][2] + bb0);
            v1.y = gt1 * (acc[mt][nt][3] + bb1);
            *(float2*)(y0 + col) = v0;
            *(float2*)(y1 + col) = v1;
        }
    }
}

// ---------------- 6: combine  out[t] = sum of 4 partials ----------------
__global__ __launch_bounds__(256) void combine_kernel(float4* __restrict__ out) {
    int t = blockIdx.x;
    int s0 = g_tok_slot[2 * t], s1 = g_tok_slot[2 * t + 1];
    int i = threadIdx.x;
    float4 a  = ((const float4*)(g_y  + (size_t)s0 * DMODEL))[i];
    float4 a2 = ((const float4*)(g_y2 + (size_t)s0 * DMODEL))[i];
    float4 b  = ((const float4*)(g_y  + (size_t)s1 * DMODEL))[i];
    float4 b2 = ((const float4*)(g_y2 + (size_t)s1 * DMODEL))[i];
    float4 r;
    r.x = (a.x + a2.x) + (b.x + b2.x);
    r.y = (a.y + a2.y) + (b.y + b2.y);
    r.z = (a.z + a2.z) + (b.z + b2.z);
    r.w = (a.w + a2.w) + (b.w + b2.w);
    out[(size_t)t * (DMODEL / 4) + i] = r;
}

// ---------------- launch ----------------
extern "C" void kernel_launch(void* const* d_in, const int* in_sizes, int n_in,
                              void* d_out, int out_size)
{
    (void)in_sizes; (void)n_in; (void)out_size;
    const float* x       = (const float*)d_in[0];
    const float* noise_u = (const float*)d_in[1];
    const float* wg      = (const float*)d_in[2];
    const float* bg      = (const float*)d_in[3];
    const float* wn      = (const float*)d_in[4];
    const float* bn      = (const float*)d_in[5];
    const float* w1      = (const float*)d_in[6];
    const float* b1      = (const float*)d_in[7];
    const float* w2      = (const float*)d_in[8];
    const float* b2      = (const float*)d_in[9];
    float* out = (float*)d_out;

    cudaFuncSetAttribute(gemm1_kernel, cudaFuncAttributeMaxDynamicSharedMemorySize, SMEM_BYTES);
    cudaFuncSetAttribute(gemm2_kernel, cudaFuncAttributeMaxDynamicSharedMemorySize, SMEM_BYTES);

    prep_kernel<<<PREP_TOTAL, 256>>>(x, w1, w2);                   // launch 0
    router_kernel<<<T_TOK / 8, 256>>>(x, noise_u, wg, bg, wn, bn); // launch 1
    offsets_scatter_kernel<<<1, 256>>>();                          // launch 2
    gemm1_kernel<<<dim3(DFF / 128, MAX_TILES), NTHR, SMEM_BYTES>>>(b1);       // launch 3 -> ncu slot
    gemm2_kernel<<<dim3(DMODEL / 128, MAX_TILES, 2), NTHR, SMEM_BYTES>>>(b2); // split-K=2
    combine_kernel<<<T_TOK, 256>>>((float4*)out);
}